// round 2
// baseline (speedup 1.0000x reference)
#include <cuda_runtime.h>
#include <math.h>

// Problem constants (fixed shapes from setup_inputs)
constexpr int B_  = 4;
constexpr int C_  = 512;   // channels (h path)
constexpr int KP_ = 512;   // key planes (f/g path)
constexpr int N_  = 4096;  // H*W
constexpr int M_  = 4096;  // HS*WS

// -------- device scratch (no allocations allowed) --------
__device__ float g_F [(size_t)B_ * KP_ * N_];   // [b][k][n]
__device__ float g_G [(size_t)B_ * KP_ * M_];   // [b][k][m]
__device__ float g_Hs[(size_t)B_ * M_  * C_];   // [b][m][c]
__device__ float g_S [(size_t)B_ * N_  * M_];   // [b][n][m]  (268 MB)
__device__ float g_mean[(size_t)B_ * N_ * C_];  // [b][n][c]
__device__ float g_e2 [(size_t)B_ * N_ * C_];   // [b][n][c]

// ============================================================
// Projection: Out[b][k][l] = sum_c W[k][c] * X[b][c][l] + bias[k]
// TSTORE: store transposed as Out[b][l][k] (used for Hs).
// Ci = Co = 512 always, L = 4096 always.
// ============================================================
template<bool TSTORE>
__global__ __launch_bounds__(256) void proj_kernel(
    const float* __restrict__ X,
    const float* __restrict__ W,
    const float* __restrict__ bias,
    int which)  // 0 -> g_F, 1 -> g_G, 2 -> g_Hs
{
    constexpr int BM = 128, BN = 128, BK = 16;
    constexpr int Ci = 512, Co = 512, L = 4096;
    __shared__ float Ws[BK][BM + 4];  // transposed W tile: Ws[c][k]
    __shared__ float Xs[BK][BN];

    float* Out = (which == 0) ? g_F : (which == 1) ? g_G : g_Hs;

    const int b  = blockIdx.z;
    const int k0 = blockIdx.y * BM;
    const int l0 = blockIdx.x * BN;
    const int tid = threadIdx.x;
    const int tm = tid >> 4;    // 0..15 : row group of 8
    const int tn = tid & 15;    // 0..15 : col group of 8

    const float* Xb = X + (size_t)b * Ci * L;

    float acc[8][8];
#pragma unroll
    for (int i = 0; i < 8; i++)
#pragma unroll
        for (int j = 0; j < 8; j++) acc[i][j] = 0.f;

    for (int kb = 0; kb < Ci; kb += BK) {
        // --- load W tile (transposed into smem) ---
        {
            const int r = tid >> 2;   // 0..63
            const int q = tid & 3;    // 0..3
#pragma unroll
            for (int p = 0; p < 2; p++) {
                const int row = r + p * 64;
                float4 w4 = *(const float4*)&W[(size_t)(k0 + row) * Ci + kb + q * 4];
                Ws[q * 4 + 0][row] = w4.x;
                Ws[q * 4 + 1][row] = w4.y;
                Ws[q * 4 + 2][row] = w4.z;
                Ws[q * 4 + 3][row] = w4.w;
            }
        }
        // --- load X tile ---
        {
            const int r  = tid >> 5;          // 0..7
            const int cq = (tid & 31) * 4;
#pragma unroll
            for (int p = 0; p < 2; p++) {
                const int row = r + p * 8;
                *(float4*)&Xs[row][cq] =
                    *(const float4*)&Xb[(size_t)(kb + row) * L + l0 + cq];
            }
        }
        __syncthreads();
#pragma unroll
        for (int kk = 0; kk < BK; kk++) {
            float a[8], bb[8];
            *(float4*)&a[0]  = *(float4*)&Ws[kk][tm * 8];
            *(float4*)&a[4]  = *(float4*)&Ws[kk][tm * 8 + 4];
            *(float4*)&bb[0] = *(float4*)&Xs[kk][tn * 8];
            *(float4*)&bb[4] = *(float4*)&Xs[kk][tn * 8 + 4];
#pragma unroll
            for (int i = 0; i < 8; i++)
#pragma unroll
                for (int j = 0; j < 8; j++)
                    acc[i][j] = fmaf(a[i], bb[j], acc[i][j]);
        }
        __syncthreads();
    }

    if (!TSTORE) {
        float* Ob = Out + (size_t)b * Co * L;
#pragma unroll
        for (int i = 0; i < 8; i++) {
            const int k = k0 + tm * 8 + i;
            const float bv = bias[k];
            float4 o0 = make_float4(acc[i][0] + bv, acc[i][1] + bv,
                                    acc[i][2] + bv, acc[i][3] + bv);
            float4 o1 = make_float4(acc[i][4] + bv, acc[i][5] + bv,
                                    acc[i][6] + bv, acc[i][7] + bv);
            *(float4*)&Ob[(size_t)k * L + l0 + tn * 8]     = o0;
            *(float4*)&Ob[(size_t)k * L + l0 + tn * 8 + 4] = o1;
        }
    } else {
        float* Ob = Out + (size_t)b * (size_t)L * Co;
#pragma unroll
        for (int j = 0; j < 8; j++) {
            const int l = l0 + tn * 8 + j;
#pragma unroll
            for (int i = 0; i < 8; i++) {
                const int k = k0 + tm * 8 + i;
                Ob[(size_t)l * Co + k] = acc[i][j] + bias[k];
            }
        }
    }
}

// ============================================================
// Logits: S[b][n][m] = sum_k F[b][k][n] * G[b][k][m]
// ============================================================
__global__ __launch_bounds__(256) void logits_kernel()
{
    constexpr int BM = 128, BN = 128, BK = 16;
    __shared__ float As[BK][BM];
    __shared__ float Bs[BK][BN];

    const int b  = blockIdx.z;
    const int n0 = blockIdx.y * BM;
    const int m0 = blockIdx.x * BN;
    const int tid = threadIdx.x;
    const int tm = tid >> 4, tn = tid & 15;

    const float* Fb = g_F + (size_t)b * KP_ * N_;
    const float* Gb = g_G + (size_t)b * KP_ * M_;

    float acc[8][8];
#pragma unroll
    for (int i = 0; i < 8; i++)
#pragma unroll
        for (int j = 0; j < 8; j++) acc[i][j] = 0.f;

    for (int kb = 0; kb < KP_; kb += BK) {
        const int r  = tid >> 5;
        const int cq = (tid & 31) * 4;
#pragma unroll
        for (int p = 0; p < 2; p++) {
            const int row = r + p * 8;
            *(float4*)&As[row][cq] =
                *(const float4*)&Fb[(size_t)(kb + row) * N_ + n0 + cq];
            *(float4*)&Bs[row][cq] =
                *(const float4*)&Gb[(size_t)(kb + row) * M_ + m0 + cq];
        }
        __syncthreads();
#pragma unroll
        for (int kk = 0; kk < BK; kk++) {
            float a[8], bb[8];
            *(float4*)&a[0]  = *(float4*)&As[kk][tm * 8];
            *(float4*)&a[4]  = *(float4*)&As[kk][tm * 8 + 4];
            *(float4*)&bb[0] = *(float4*)&Bs[kk][tn * 8];
            *(float4*)&bb[4] = *(float4*)&Bs[kk][tn * 8 + 4];
#pragma unroll
            for (int i = 0; i < 8; i++)
#pragma unroll
                for (int j = 0; j < 8; j++)
                    acc[i][j] = fmaf(a[i], bb[j], acc[i][j]);
        }
        __syncthreads();
    }

    float* Sb = g_S + (size_t)b * N_ * M_;
#pragma unroll
    for (int i = 0; i < 8; i++) {
        const int n = n0 + tm * 8 + i;
        *(float4*)&Sb[(size_t)n * M_ + m0 + tn * 8]     = *(float4*)&acc[i][0];
        *(float4*)&Sb[(size_t)n * M_ + m0 + tn * 8 + 4] = *(float4*)&acc[i][4];
    }
}

// ============================================================
// Softmax over last dim (M = 4096), one block (256 thr) per row.
// Row held in registers: 1 read + 1 write of S.
// ============================================================
__global__ __launch_bounds__(256) void softmax_kernel()
{
    const size_t row = blockIdx.x;            // 0 .. B*N-1
    float4* p = (float4*)(g_S + row * (size_t)M_);
    const int t = threadIdx.x;

    float4 v[4];
    float mx = -INFINITY;
#pragma unroll
    for (int i = 0; i < 4; i++) {
        v[i] = p[i * 256 + t];
        mx = fmaxf(mx, fmaxf(fmaxf(v[i].x, v[i].y), fmaxf(v[i].z, v[i].w)));
    }

    __shared__ float red[256];
    red[t] = mx;
    __syncthreads();
#pragma unroll
    for (int s = 128; s >= 1; s >>= 1) {
        if (t < s) red[t] = fmaxf(red[t], red[t + s]);
        __syncthreads();
    }
    mx = red[0];
    __syncthreads();

    float sum = 0.f;
#pragma unroll
    for (int i = 0; i < 4; i++) {
        v[i].x = __expf(v[i].x - mx);
        v[i].y = __expf(v[i].y - mx);
        v[i].z = __expf(v[i].z - mx);
        v[i].w = __expf(v[i].w - mx);
        sum += (v[i].x + v[i].y) + (v[i].z + v[i].w);
    }
    red[t] = sum;
    __syncthreads();
#pragma unroll
    for (int s = 128; s >= 1; s >>= 1) {
        if (t < s) red[t] += red[t + s];
        __syncthreads();
    }
    const float inv = 1.f / red[0];

#pragma unroll
    for (int i = 0; i < 4; i++) {
        v[i].x *= inv; v[i].y *= inv; v[i].z *= inv; v[i].w *= inv;
        p[i * 256 + t] = v[i];
    }
}

// ============================================================
// mean/e2: Mean[b][n][c] = sum_m S[b][n][m] * Hs[b][m][c]
//          E2  [b][n][c] = sum_m S[b][n][m] * Hs[b][m][c]^2
// ============================================================
__global__ __launch_bounds__(256) void meane2_kernel()
{
    constexpr int BM = 128, BN = 64, BK = 16;
    __shared__ float As[BK][BM + 4];  // transposed S tile: As[m][n]
    __shared__ float Bs[BK][BN];

    const int b  = blockIdx.z;
    const int n0 = blockIdx.y * BM;
    const int c0 = blockIdx.x * BN;
    const int tid = threadIdx.x;
    const int tm = tid >> 4;   // 0..15 -> 8 rows each
    const int tn = tid & 15;   // 0..15 -> 4 cols each

    const float* Sb = g_S  + (size_t)b * N_ * M_;
    const float* Hb = g_Hs + (size_t)b * M_ * C_;

    float acc1[8][4], acc2[8][4];
#pragma unroll
    for (int i = 0; i < 8; i++)
#pragma unroll
        for (int j = 0; j < 4; j++) { acc1[i][j] = 0.f; acc2[i][j] = 0.f; }

    for (int kb = 0; kb < M_; kb += BK) {
        // --- S tile, transposed load ---
        {
            const int r = tid >> 2;   // 0..63
            const int q = tid & 3;    // 0..3
#pragma unroll
            for (int p = 0; p < 2; p++) {
                const int row = r + p * 64;
                float4 s4 = *(const float4*)&Sb[(size_t)(n0 + row) * M_ + kb + q * 4];
                As[q * 4 + 0][row] = s4.x;
                As[q * 4 + 1][row] = s4.y;
                As[q * 4 + 2][row] = s4.z;
                As[q * 4 + 3][row] = s4.w;
            }
        }
        // --- Hs tile ---
        {
            const int rr = tid >> 4;          // 0..15
            const int cc = (tid & 15) * 4;    // 0..60
            *(float4*)&Bs[rr][cc] =
                *(const float4*)&Hb[(size_t)(kb + rr) * C_ + c0 + cc];
        }
        __syncthreads();
#pragma unroll
        for (int kk = 0; kk < BK; kk++) {
            float a[8], bb[4], b2[4];
            *(float4*)&a[0]  = *(float4*)&As[kk][tm * 8];
            *(float4*)&a[4]  = *(float4*)&As[kk][tm * 8 + 4];
            *(float4*)&bb[0] = *(float4*)&Bs[kk][tn * 4];
#pragma unroll
            for (int j = 0; j < 4; j++) b2[j] = bb[j] * bb[j];
#pragma unroll
            for (int i = 0; i < 8; i++)
#pragma unroll
                for (int j = 0; j < 4; j++) {
                    acc1[i][j] = fmaf(a[i], bb[j], acc1[i][j]);
                    acc2[i][j] = fmaf(a[i], b2[j], acc2[i][j]);
                }
        }
        __syncthreads();
    }

#pragma unroll
    for (int i = 0; i < 8; i++) {
        const int n = n0 + tm * 8 + i;
        const size_t base = ((size_t)b * N_ + n) * C_ + c0 + tn * 4;
        *(float4*)&g_mean[base] = *(float4*)&acc1[i][0];
        *(float4*)&g_e2[base]   = *(float4*)&acc2[i][0];
    }
}

// ============================================================
// Epilogue: out[b][c][n] = sqrt(relu(e2 - mean^2)) * c_x[b][c][n] + mean
// mean/e2 stored [b][n][c] -> 32x32 smem tile transpose.
// ============================================================
__global__ void epilogue_kernel(const float* __restrict__ c_x,
                                float* __restrict__ out)
{
    __shared__ float sm[32][33];
    __shared__ float ss[32][33];
    const int b  = blockIdx.z;
    const int c0 = blockIdx.y * 32;
    const int n0 = blockIdx.x * 32;

    for (int i = threadIdx.y; i < 32; i += 8) {
        const int n = n0 + i;
        const int c = c0 + threadIdx.x;
        const size_t idx = ((size_t)b * N_ + n) * C_ + c;
        const float m = g_mean[idx];
        const float e = g_e2[idx];
        float v = e - m * m;
        v = (v > 0.f) ? sqrtf(v) : 0.f;
        sm[i][threadIdx.x] = m;
        ss[i][threadIdx.x] = v;
    }
    __syncthreads();
    for (int i = threadIdx.y; i < 32; i += 8) {
        const int c = c0 + i;
        const int n = n0 + threadIdx.x;
        const size_t idx = ((size_t)b * C_ + c) * N_ + n;
        out[idx] = ss[threadIdx.x][i] * c_x[idx] + sm[threadIdx.x][i];
    }
}

// ============================================================
extern "C" void kernel_launch(void* const* d_in, const int* in_sizes, int n_in,
                              void* d_out, int out_size)
{
    const float* c_x  = (const float*)d_in[0];
    const float* s_x  = (const float*)d_in[1];
    const float* c_1x = (const float*)d_in[2];
    const float* s_1x = (const float*)d_in[3];
    const float* f_w  = (const float*)d_in[4];
    const float* f_b  = (const float*)d_in[5];
    const float* g_w  = (const float*)d_in[6];
    const float* g_b  = (const float*)d_in[7];
    const float* h_w  = (const float*)d_in[8];
    const float* h_b  = (const float*)d_in[9];
    float* out = (float*)d_out;

    // projections
    proj_kernel<false><<<dim3(N_ / 128, KP_ / 128, B_), 256>>>(c_1x, f_w, f_b, 0);
    proj_kernel<false><<<dim3(M_ / 128, KP_ / 128, B_), 256>>>(s_1x, g_w, g_b, 1);
    proj_kernel<true ><<<dim3(M_ / 128, C_  / 128, B_), 256>>>(s_x,  h_w, h_b, 2);

    // attention logits
    logits_kernel<<<dim3(M_ / 128, N_ / 128, B_), 256>>>();

    // softmax
    softmax_kernel<<<B_ * N_, 256>>>();

    // weighted mean / second moment
    meane2_kernel<<<dim3(C_ / 64, N_ / 128, B_), 256>>>();

    // final affine
    epilogue_kernel<<<dim3(N_ / 32, C_ / 32, B_), dim3(32, 8)>>>(c_x, out);
}

// round 4
// speedup vs baseline: 1.0025x; 1.0025x over previous
#include <cuda_runtime.h>
#include <math.h>

// Problem constants (fixed shapes from setup_inputs)
constexpr int B_  = 4;
constexpr int C_  = 512;   // channels (h path)
constexpr int KP_ = 512;   // key planes (f/g path)
constexpr int N_  = 4096;  // H*W
constexpr int M_  = 4096;  // HS*WS

// -------- device scratch (no allocations allowed) --------
__device__ float g_F [(size_t)B_ * KP_ * N_];   // [b][k][n]
__device__ float g_G [(size_t)B_ * KP_ * M_];   // [b][k][m]
__device__ float g_Hs[(size_t)B_ * M_  * C_];   // [b][m][c]
__device__ float g_S [(size_t)B_ * N_  * M_];   // [b][n][m]  (268 MB)
__device__ float g_mean[(size_t)B_ * N_ * C_];  // [b][n][c]
__device__ float g_e2 [(size_t)B_ * N_ * C_];   // [b][n][c]

// ============================================================
// Projection: Out[b][k][l] = sum_c W[k][c] * X[b][c][l] + bias[k]
// TSTORE: store transposed as Out[b][l][k] (used for Hs).
// Ci = Co = 512 always, L = 4096 always.
// ============================================================
template<bool TSTORE>
__global__ __launch_bounds__(256) void proj_kernel(
    const float* __restrict__ X,
    const float* __restrict__ W,
    const float* __restrict__ bias,
    int which)  // 0 -> g_F, 1 -> g_G, 2 -> g_Hs
{
    constexpr int BM = 128, BN = 128, BK = 16;
    constexpr int Ci = 512, Co = 512, L = 4096;
    __shared__ float Ws[BK][BM + 4];  // transposed W tile: Ws[c][k]
    __shared__ float Xs[BK][BN];

    float* Out = (which == 0) ? g_F : (which == 1) ? g_G : g_Hs;

    const int b  = blockIdx.z;
    const int k0 = blockIdx.y * BM;
    const int l0 = blockIdx.x * BN;
    const int tid = threadIdx.x;
    const int tm = tid >> 4;    // 0..15 : row group of 8
    const int tn = tid & 15;    // 0..15 : col group of 8

    const float* Xb = X + (size_t)b * Ci * L;

    float acc[8][8];
#pragma unroll
    for (int i = 0; i < 8; i++)
#pragma unroll
        for (int j = 0; j < 8; j++) acc[i][j] = 0.f;

    for (int kb = 0; kb < Ci; kb += BK) {
        // --- load W tile (transposed into smem) ---
        {
            const int r = tid >> 2;   // 0..63
            const int q = tid & 3;    // 0..3
#pragma unroll
            for (int p = 0; p < 2; p++) {
                const int row = r + p * 64;
                float4 w4 = *(const float4*)&W[(size_t)(k0 + row) * Ci + kb + q * 4];
                Ws[q * 4 + 0][row] = w4.x;
                Ws[q * 4 + 1][row] = w4.y;
                Ws[q * 4 + 2][row] = w4.z;
                Ws[q * 4 + 3][row] = w4.w;
            }
        }
        // --- load X tile ---
        {
            const int r  = tid >> 5;          // 0..7
            const int cq = (tid & 31) * 4;
#pragma unroll
            for (int p = 0; p < 2; p++) {
                const int row = r + p * 8;
                *(float4*)&Xs[row][cq] =
                    *(const float4*)&Xb[(size_t)(kb + row) * L + l0 + cq];
            }
        }
        __syncthreads();
#pragma unroll
        for (int kk = 0; kk < BK; kk++) {
            float a[8], bb[8];
            *(float4*)&a[0]  = *(float4*)&Ws[kk][tm * 8];
            *(float4*)&a[4]  = *(float4*)&Ws[kk][tm * 8 + 4];
            *(float4*)&bb[0] = *(float4*)&Xs[kk][tn * 8];
            *(float4*)&bb[4] = *(float4*)&Xs[kk][tn * 8 + 4];
#pragma unroll
            for (int i = 0; i < 8; i++)
#pragma unroll
                for (int j = 0; j < 8; j++)
                    acc[i][j] = fmaf(a[i], bb[j], acc[i][j]);
        }
        __syncthreads();
    }

    if (!TSTORE) {
        float* Ob = Out + (size_t)b * Co * L;
#pragma unroll
        for (int i = 0; i < 8; i++) {
            const int k = k0 + tm * 8 + i;
            const float bv = bias[k];
            float4 o0 = make_float4(acc[i][0] + bv, acc[i][1] + bv,
                                    acc[i][2] + bv, acc[i][3] + bv);
            float4 o1 = make_float4(acc[i][4] + bv, acc[i][5] + bv,
                                    acc[i][6] + bv, acc[i][7] + bv);
            *(float4*)&Ob[(size_t)k * L + l0 + tn * 8]     = o0;
            *(float4*)&Ob[(size_t)k * L + l0 + tn * 8 + 4] = o1;
        }
    } else {
        float* Ob = Out + (size_t)b * (size_t)L * Co;
#pragma unroll
        for (int j = 0; j < 8; j++) {
            const int l = l0 + tn * 8 + j;
#pragma unroll
            for (int i = 0; i < 8; i++) {
                const int k = k0 + tm * 8 + i;
                Ob[(size_t)l * Co + k] = acc[i][j] + bias[k];
            }
        }
    }
}

// ============================================================
// Logits: S[b][n][m] = sum_k F[b][k][n] * G[b][k][m]
// ============================================================
__global__ __launch_bounds__(256) void logits_kernel()
{
    constexpr int BM = 128, BN = 128, BK = 16;
    __shared__ float As[BK][BM];
    __shared__ float Bs[BK][BN];

    const int b  = blockIdx.z;
    const int n0 = blockIdx.y * BM;
    const int m0 = blockIdx.x * BN;
    const int tid = threadIdx.x;
    const int tm = tid >> 4, tn = tid & 15;

    const float* Fb = g_F + (size_t)b * KP_ * N_;
    const float* Gb = g_G + (size_t)b * KP_ * M_;

    float acc[8][8];
#pragma unroll
    for (int i = 0; i < 8; i++)
#pragma unroll
        for (int j = 0; j < 8; j++) acc[i][j] = 0.f;

    for (int kb = 0; kb < KP_; kb += BK) {
        const int r  = tid >> 5;
        const int cq = (tid & 31) * 4;
#pragma unroll
        for (int p = 0; p < 2; p++) {
            const int row = r + p * 8;
            *(float4*)&As[row][cq] =
                *(const float4*)&Fb[(size_t)(kb + row) * N_ + n0 + cq];
            *(float4*)&Bs[row][cq] =
                *(const float4*)&Gb[(size_t)(kb + row) * M_ + m0 + cq];
        }
        __syncthreads();
#pragma unroll
        for (int kk = 0; kk < BK; kk++) {
            float a[8], bb[8];
            *(float4*)&a[0]  = *(float4*)&As[kk][tm * 8];
            *(float4*)&a[4]  = *(float4*)&As[kk][tm * 8 + 4];
            *(float4*)&bb[0] = *(float4*)&Bs[kk][tn * 8];
            *(float4*)&bb[4] = *(float4*)&Bs[kk][tn * 8 + 4];
#pragma unroll
            for (int i = 0; i < 8; i++)
#pragma unroll
                for (int j = 0; j < 8; j++)
                    acc[i][j] = fmaf(a[i], bb[j], acc[i][j]);
        }
        __syncthreads();
    }

    float* Sb = g_S + (size_t)b * N_ * M_;
#pragma unroll
    for (int i = 0; i < 8; i++) {
        const int n = n0 + tm * 8 + i;
        *(float4*)&Sb[(size_t)n * M_ + m0 + tn * 8]     = *(float4*)&acc[i][0];
        *(float4*)&Sb[(size_t)n * M_ + m0 + tn * 8 + 4] = *(float4*)&acc[i][4];
    }
}

// ============================================================
// Softmax over last dim (M = 4096), one block (256 thr) per row.
// Row held in registers: 1 read + 1 write of S.
// ============================================================
__global__ __launch_bounds__(256) void softmax_kernel()
{
    const size_t row = blockIdx.x;            // 0 .. B*N-1
    float4* p = (float4*)(g_S + row * (size_t)M_);
    const int t = threadIdx.x;

    float4 v[4];
    float mx = -INFINITY;
#pragma unroll
    for (int i = 0; i < 4; i++) {
        v[i] = p[i * 256 + t];
        mx = fmaxf(mx, fmaxf(fmaxf(v[i].x, v[i].y), fmaxf(v[i].z, v[i].w)));
    }

    __shared__ float red[256];
    red[t] = mx;
    __syncthreads();
#pragma unroll
    for (int s = 128; s >= 1; s >>= 1) {
        if (t < s) red[t] = fmaxf(red[t], red[t + s]);
        __syncthreads();
    }
    mx = red[0];
    __syncthreads();

    float sum = 0.f;
#pragma unroll
    for (int i = 0; i < 4; i++) {
        v[i].x = __expf(v[i].x - mx);
        v[i].y = __expf(v[i].y - mx);
        v[i].z = __expf(v[i].z - mx);
        v[i].w = __expf(v[i].w - mx);
        sum += (v[i].x + v[i].y) + (v[i].z + v[i].w);
    }
    red[t] = sum;
    __syncthreads();
#pragma unroll
    for (int s = 128; s >= 1; s >>= 1) {
        if (t < s) red[t] += red[t + s];
        __syncthreads();
    }
    const float inv = 1.f / red[0];

#pragma unroll
    for (int i = 0; i < 4; i++) {
        v[i].x *= inv; v[i].y *= inv; v[i].z *= inv; v[i].w *= inv;
        p[i * 256 + t] = v[i];
    }
}

// ============================================================
// mean/e2: Mean[b][n][c] = sum_m S[b][n][m] * Hs[b][m][c]
//          E2  [b][n][c] = sum_m S[b][n][m] * Hs[b][m][c]^2
// ============================================================
__global__ __launch_bounds__(256) void meane2_kernel()
{
    constexpr int BM = 128, BN = 64, BK = 16;
    __shared__ float As[BK][BM + 4];  // transposed S tile: As[m][n]
    __shared__ float Bs[BK][BN];

    const int b  = blockIdx.z;
    const int n0 = blockIdx.y * BM;
    const int c0 = blockIdx.x * BN;
    const int tid = threadIdx.x;
    const int tm = tid >> 4;   // 0..15 -> 8 rows each
    const int tn = tid & 15;   // 0..15 -> 4 cols each

    const float* Sb = g_S  + (size_t)b * N_ * M_;
    const float* Hb = g_Hs + (size_t)b * M_ * C_;

    float acc1[8][4], acc2[8][4];
#pragma unroll
    for (int i = 0; i < 8; i++)
#pragma unroll
        for (int j = 0; j < 4; j++) { acc1[i][j] = 0.f; acc2[i][j] = 0.f; }

    for (int kb = 0; kb < M_; kb += BK) {
        // --- S tile, transposed load ---
        {
            const int r = tid >> 2;   // 0..63
            const int q = tid & 3;    // 0..3
#pragma unroll
            for (int p = 0; p < 2; p++) {
                const int row = r + p * 64;
                float4 s4 = *(const float4*)&Sb[(size_t)(n0 + row) * M_ + kb + q * 4];
                As[q * 4 + 0][row] = s4.x;
                As[q * 4 + 1][row] = s4.y;
                As[q * 4 + 2][row] = s4.z;
                As[q * 4 + 3][row] = s4.w;
            }
        }
        // --- Hs tile ---
        {
            const int rr = tid >> 4;          // 0..15
            const int cc = (tid & 15) * 4;    // 0..60
            *(float4*)&Bs[rr][cc] =
                *(const float4*)&Hb[(size_t)(kb + rr) * C_ + c0 + cc];
        }
        __syncthreads();
#pragma unroll
        for (int kk = 0; kk < BK; kk++) {
            float a[8], bb[4], b2[4];
            *(float4*)&a[0]  = *(float4*)&As[kk][tm * 8];
            *(float4*)&a[4]  = *(float4*)&As[kk][tm * 8 + 4];
            *(float4*)&bb[0] = *(float4*)&Bs[kk][tn * 4];
#pragma unroll
            for (int j = 0; j < 4; j++) b2[j] = bb[j] * bb[j];
#pragma unroll
            for (int i = 0; i < 8; i++)
#pragma unroll
                for (int j = 0; j < 4; j++) {
                    acc1[i][j] = fmaf(a[i], bb[j], acc1[i][j]);
                    acc2[i][j] = fmaf(a[i], b2[j], acc2[i][j]);
                }
        }
        __syncthreads();
    }

#pragma unroll
    for (int i = 0; i < 8; i++) {
        const int n = n0 + tm * 8 + i;
        const size_t base = ((size_t)b * N_ + n) * C_ + c0 + tn * 4;
        *(float4*)&g_mean[base] = *(float4*)&acc1[i][0];
        *(float4*)&g_e2[base]   = *(float4*)&acc2[i][0];
    }
}

// ============================================================
// Epilogue: out[b][c][n] = sqrt(relu(e2 - mean^2)) * c_x[b][c][n] + mean
// mean/e2 stored [b][n][c] -> 32x32 smem tile transpose.
// ============================================================
__global__ void epilogue_kernel(const float* __restrict__ c_x,
                                float* __restrict__ out)
{
    __shared__ float sm[32][33];
    __shared__ float ss[32][33];
    const int b  = blockIdx.z;
    const int c0 = blockIdx.y * 32;
    const int n0 = blockIdx.x * 32;

    for (int i = threadIdx.y; i < 32; i += 8) {
        const int n = n0 + i;
        const int c = c0 + threadIdx.x;
        const size_t idx = ((size_t)b * N_ + n) * C_ + c;
        const float m = g_mean[idx];
        const float e = g_e2[idx];
        float v = e - m * m;
        v = (v > 0.f) ? sqrtf(v) : 0.f;
        sm[i][threadIdx.x] = m;
        ss[i][threadIdx.x] = v;
    }
    __syncthreads();
    for (int i = threadIdx.y; i < 32; i += 8) {
        const int c = c0 + i;
        const int n = n0 + threadIdx.x;
        const size_t idx = ((size_t)b * C_ + c) * N_ + n;
        out[idx] = ss[threadIdx.x][i] * c_x[idx] + sm[threadIdx.x][i];
    }
}

// ============================================================
extern "C" void kernel_launch(void* const* d_in, const int* in_sizes, int n_in,
                              void* d_out, int out_size)
{
    const float* c_x  = (const float*)d_in[0];
    const float* s_x  = (const float*)d_in[1];
    const float* c_1x = (const float*)d_in[2];
    const float* s_1x = (const float*)d_in[3];
    const float* f_w  = (const float*)d_in[4];
    const float* f_b  = (const float*)d_in[5];
    const float* g_w  = (const float*)d_in[6];
    const float* g_b  = (const float*)d_in[7];
    const float* h_w  = (const float*)d_in[8];
    const float* h_b  = (const float*)d_in[9];
    float* out = (float*)d_out;

    // projections
    proj_kernel<false><<<dim3(N_ / 128, KP_ / 128, B_), 256>>>(c_1x, f_w, f_b, 0);
    proj_kernel<false><<<dim3(M_ / 128, KP_ / 128, B_), 256>>>(s_1x, g_w, g_b, 1);
    proj_kernel<true ><<<dim3(M_ / 128, C_  / 128, B_), 256>>>(s_x,  h_w, h_b, 2);

    // attention logits
    logits_kernel<<<dim3(M_ / 128, N_ / 128, B_), 256>>>();

    // softmax
    softmax_kernel<<<B_ * N_, 256>>>();

    // weighted mean / second moment
    meane2_kernel<<<dim3(C_ / 64, N_ / 128, B_), 256>>>();

    // final affine
    epilogue_kernel<<<dim3(N_ / 32, C_ / 32, B_), dim3(32, 8)>>>(c_x, out);
}